// round 2
// baseline (speedup 1.0000x reference)
#include <cuda_runtime.h>

// CompetitiveLayer: K = sqrt_K^2; 31 iterations of
//   AF = AT / (1 + BF @ K^T);  BF = BT / (1 + AF @ K)
// then C[b,i,j] = AF[b,i] * K[i,j] * BF[b,j].
//
// One CTA owns 64 B-rows. AF/BF live in REGISTERS (4x4 tile per thread);
// the row-broadcast needed by each GEMV is intra-warp (rows 4*ty..4*ty+3 are
// owned by 16 lanes of one warp half) and done with __shfl_sync. K and K^T
// live in static shared (conflict-free float4 reads). No block barriers in
// the mainloop; exactly 48 KB static smem; kernel_launch is a bare launch.

#define ITERS 31

__global__ __launch_bounds__(256, 1)
void comp_layer_kernel(const float* __restrict__ AT,
                       const float* __restrict__ BT,
                       const float* __restrict__ sqrtK,
                       float* __restrict__ C)
{
    __shared__ float Ksh[4096];   // K[i][j]            (kept for BF update + C)
    __shared__ float KTsh[4096];  // K^T: [j][i]        (reused for final AF)
    __shared__ float BFsh[4096];  // final BF scratch

    const int t    = threadIdx.x;        // 0..255
    const int tx   = t & 15;             // column group (4 cols)
    const int ty   = t >> 4;             // row group    (4 rows)
    const int lane = t & 31;
    const int row0 = blockIdx.x << 6;

    // ---- K = sqrt_K^2, both orientations ----
    #pragma unroll
    for (int idx = t; idx < 4096; idx += 256) {
        float v = sqrtK[idx];
        v *= v;
        Ksh[idx] = v;
        KTsh[((idx & 63) << 6) | (idx >> 6)] = v;
    }
    __syncthreads();

    // ---- AT/BT tiles in registers; BF initialized to BT (scan carry) ----
    float at[4][4], bt[4][4], af[4][4], bf[4][4];
    #pragma unroll
    for (int rr = 0; rr < 4; ++rr) {
        const int gr = row0 + 4 * ty + rr;
        float4 a4 = *(const float4*)&AT[(gr << 6) + (tx << 2)];
        float4 b4 = *(const float4*)&BT[(gr << 6) + (tx << 2)];
        at[rr][0] = a4.x; at[rr][1] = a4.y; at[rr][2] = a4.z; at[rr][3] = a4.w;
        bt[rr][0] = b4.x; bt[rr][1] = b4.y; bt[rr][2] = b4.z; bt[rr][3] = b4.w;
        #pragma unroll
        for (int cc = 0; cc < 4; ++cc) bf[rr][cc] = bt[rr][cc];
    }

    const float* ktp = KTsh + (tx << 2);
    const float* kp  = Ksh  + (tx << 2);

    #pragma unroll 1
    for (int it = 0; it < ITERS; ++it) {
        // ---- AF[r][c] = AT[r][c] / (1 + sum_j BF[r][j] * K[c][j]) ----
        {
            float acc[4][4];
            #pragma unroll
            for (int rr = 0; rr < 4; ++rr)
                #pragma unroll
                for (int cc = 0; cc < 4; ++cc) acc[rr][cc] = 0.0f;

            #pragma unroll 2
            for (int j4 = 0; j4 < 16; ++j4) {
                const int src = (lane & 16) | j4;   // owner lane of cols 4*j4..4*j4+3
                #pragma unroll
                for (int jj = 0; jj < 4; ++jj) {
                    const int j = (j4 << 2) | jj;
                    float4 kv = *(const float4*)(ktp + (j << 6));  // K^T[j][4tx..]
                    float b0 = __shfl_sync(0xffffffffu, bf[0][jj], src);
                    float b1 = __shfl_sync(0xffffffffu, bf[1][jj], src);
                    float b2 = __shfl_sync(0xffffffffu, bf[2][jj], src);
                    float b3 = __shfl_sync(0xffffffffu, bf[3][jj], src);
                    acc[0][0] += b0 * kv.x; acc[0][1] += b0 * kv.y; acc[0][2] += b0 * kv.z; acc[0][3] += b0 * kv.w;
                    acc[1][0] += b1 * kv.x; acc[1][1] += b1 * kv.y; acc[1][2] += b1 * kv.z; acc[1][3] += b1 * kv.w;
                    acc[2][0] += b2 * kv.x; acc[2][1] += b2 * kv.y; acc[2][2] += b2 * kv.z; acc[2][3] += b2 * kv.w;
                    acc[3][0] += b3 * kv.x; acc[3][1] += b3 * kv.y; acc[3][2] += b3 * kv.z; acc[3][3] += b3 * kv.w;
                }
            }
            #pragma unroll
            for (int rr = 0; rr < 4; ++rr)
                #pragma unroll
                for (int cc = 0; cc < 4; ++cc)
                    af[rr][cc] = __fdividef(at[rr][cc], 1.0f + acc[rr][cc]);
        }

        // ---- BF[r][c] = BT[r][c] / (1 + sum_i AF[r][i] * K[i][c]) ----
        {
            float acc[4][4];
            #pragma unroll
            for (int rr = 0; rr < 4; ++rr)
                #pragma unroll
                for (int cc = 0; cc < 4; ++cc) acc[rr][cc] = 0.0f;

            #pragma unroll 2
            for (int i4 = 0; i4 < 16; ++i4) {
                const int src = (lane & 16) | i4;
                #pragma unroll
                for (int ii = 0; ii < 4; ++ii) {
                    const int i = (i4 << 2) | ii;
                    float4 kv = *(const float4*)(kp + (i << 6));   // K[i][4tx..]
                    float a0 = __shfl_sync(0xffffffffu, af[0][ii], src);
                    float a1 = __shfl_sync(0xffffffffu, af[1][ii], src);
                    float a2 = __shfl_sync(0xffffffffu, af[2][ii], src);
                    float a3 = __shfl_sync(0xffffffffu, af[3][ii], src);
                    acc[0][0] += a0 * kv.x; acc[0][1] += a0 * kv.y; acc[0][2] += a0 * kv.z; acc[0][3] += a0 * kv.w;
                    acc[1][0] += a1 * kv.x; acc[1][1] += a1 * kv.y; acc[1][2] += a1 * kv.z; acc[1][3] += a1 * kv.w;
                    acc[2][0] += a2 * kv.x; acc[2][1] += a2 * kv.y; acc[2][2] += a2 * kv.z; acc[2][3] += a2 * kv.w;
                    acc[3][0] += a3 * kv.x; acc[3][1] += a3 * kv.y; acc[3][2] += a3 * kv.z; acc[3][3] += a3 * kv.w;
                }
            }
            #pragma unroll
            for (int rr = 0; rr < 4; ++rr)
                #pragma unroll
                for (int cc = 0; cc < 4; ++cc)
                    bf[rr][cc] = __fdividef(bt[rr][cc], 1.0f + acc[rr][cc]);
        }
    }

    // ---- park final AF/BF in shared (KTsh reused for AF) ----
    __syncthreads();   // all warps done reading KTsh before overwrite
    #pragma unroll
    for (int rr = 0; rr < 4; ++rr) {
        const int off = ((4 * ty + rr) << 6) + (tx << 2);
        *(float4*)&KTsh[off] = make_float4(af[rr][0], af[rr][1], af[rr][2], af[rr][3]);
        *(float4*)&BFsh[off] = make_float4(bf[rr][0], bf[rr][1], bf[rr][2], bf[rr][3]);
    }
    __syncthreads();

    // ---- C[r][i][j] = AF[r][i] * K[i][j] * BF[r][j] ----
    #pragma unroll 1
    for (int r = 0; r < 64; ++r) {
        float* crow = C + ((size_t)(row0 + r) << 12);   // 4096 floats / row
        const float* afr = &KTsh[r << 6];
        const float* bfr = &BFsh[r << 6];
        #pragma unroll
        for (int q = 0; q < 4; ++q) {
            const int e = ((q << 8) + t) << 2;          // 0..4092 step 4
            const int i = e >> 6;
            const int j = e & 63;
            const float a = afr[i];
            float4 k4 = *(const float4*)&Ksh[e];        // K[i][j..j+3] (e = i*64+j)
            float4 b4 = *(const float4*)&bfr[j];
            float4 o;
            o.x = a * k4.x * b4.x;
            o.y = a * k4.y * b4.y;
            o.z = a * k4.z * b4.z;
            o.w = a * k4.w * b4.w;
            *(float4*)&crow[e] = o;
        }
    }
}

extern "C" void kernel_launch(void* const* d_in, const int* in_sizes, int n_in,
                              void* d_out, int out_size)
{
    const float* AT = (const float*)d_in[0];   // (8192, 64)
    const float* BT = (const float*)d_in[1];   // (8192, 64)
    const float* sK = (const float*)d_in[2];   // (64, 64)
    float* C = (float*)d_out;                  // (8192, 64, 64)

    comp_layer_kernel<<<128, 256>>>(AT, BT, sK, C);
}

// round 4
// speedup vs baseline: 1.1535x; 1.1535x over previous
#include <cuda_runtime.h>
#include <cstdint>

// CompetitiveLayer: K = sqrt_K^2; fixed-point iterations of
//   AF = AT / (1 + BF @ K^T);  BF = BT / (1 + AF @ K)
// then C[b,i,j] = AF[b,i] * K[i,j] * BF[b,j].
//
// One CTA owns 64 B-rows, 256 threads, 4x4 register tile per thread.
// AF/BF live in shared in DUPLICATED-PAIR layout (v,v) so the GEMV scalar
// operand is a broadcast ld.shared.b64 feeding packed fma.rn.f32x2 directly
// (no shuffles, no packing MOVs). K and K^T rows are read as ld.shared.v2.b64.
// Rows are warp-private -> only __syncwarp() in the mainloop.

#define ITERS  24      // 23 no-grad solve iters + 1 differentiable iter
#define DUPSTR 132     // dup-row stride in floats (pair layout, bank-spread)

#define OFF_K   0
#define OFF_KT  4096
#define OFF_AFD 8192
#define OFF_BFD (8192 + 64 * DUPSTR)
#define SMEM_FLOATS (8192 + 2 * 64 * DUPSTR)   // 25088 floats = 100352 B

typedef unsigned long long u64t;

__device__ __forceinline__ u64t ffma2(u64t a, u64t b, u64t c) {
    u64t d;
    asm("fma.rn.f32x2 %0, %1, %2, %3;" : "=l"(d) : "l"(a), "l"(b), "l"(c));
    return d;
}
__device__ __forceinline__ void lds_v2u64(uint32_t addr, u64t& a, u64t& b) {
    asm("ld.shared.v2.b64 {%0, %1}, [%2];" : "=l"(a), "=l"(b) : "r"(addr));
}
__device__ __forceinline__ u64t lds_u64(uint32_t addr) {
    u64t v;
    asm("ld.shared.b64 %0, [%1];" : "=l"(v) : "r"(addr));
    return v;
}
__device__ __forceinline__ void unpack2(u64t v, float& lo, float& hi) {
    asm("mov.b64 {%0, %1}, %2;" : "=f"(lo), "=f"(hi) : "l"(v));
}

extern __shared__ float sm[];

__global__ __launch_bounds__(256, 1)
void comp_layer_kernel(const float* __restrict__ AT,
                       const float* __restrict__ BT,
                       const float* __restrict__ sqrtK,
                       float* __restrict__ C)
{
    const int t    = threadIdx.x;        // 0..255
    const int tx   = t & 15;             // column group (4 cols)
    const int ty   = t >> 4;             // row group    (4 rows)
    const int row0 = blockIdx.x << 6;

    float* Ksh  = sm + OFF_K;
    float* KTsh = sm + OFF_KT;
    float* AFd  = sm + OFF_AFD;
    float* BFd  = sm + OFF_BFD;

    // ---- K = sqrt_K^2 in both orientations ----
    #pragma unroll
    for (int idx = t; idx < 4096; idx += 256) {
        float v = sqrtK[idx];
        v *= v;
        Ksh[idx] = v;
        KTsh[((idx & 63) << 6) | (idx >> 6)] = v;
    }

    // ---- AT/BT tiles in registers; BF dup-initialized to BT ----
    float at[4][4], bt[4][4];
    #pragma unroll
    for (int rr = 0; rr < 4; ++rr) {
        const int gr = row0 + 4 * ty + rr;
        float4 a4 = *(const float4*)&AT[(gr << 6) + (tx << 2)];
        float4 b4 = *(const float4*)&BT[(gr << 6) + (tx << 2)];
        at[rr][0] = a4.x; at[rr][1] = a4.y; at[rr][2] = a4.z; at[rr][3] = a4.w;
        bt[rr][0] = b4.x; bt[rr][1] = b4.y; bt[rr][2] = b4.z; bt[rr][3] = b4.w;
        float* dst = &BFd[(4 * ty + rr) * DUPSTR + (tx << 3)];
        *(float4*)dst       = make_float4(b4.x, b4.x, b4.y, b4.y);
        *(float4*)(dst + 4) = make_float4(b4.z, b4.z, b4.w, b4.w);
    }
    __syncthreads();

    // shared-space byte addresses
    const uint32_t ktb = (uint32_t)__cvta_generic_to_shared(KTsh) + (tx << 4);
    const uint32_t kb  = (uint32_t)__cvta_generic_to_shared(Ksh)  + (tx << 4);
    uint32_t afr[4], bfr[4];   // dup-row base addresses for this thread's rows
    #pragma unroll
    for (int rr = 0; rr < 4; ++rr) {
        afr[rr] = (uint32_t)__cvta_generic_to_shared(&AFd[(4 * ty + rr) * DUPSTR]);
        bfr[rr] = (uint32_t)__cvta_generic_to_shared(&BFd[(4 * ty + rr) * DUPSTR]);
    }

    float aflast[4][4], bflast[4][4];

    #pragma unroll 1
    for (int it = 0; it < ITERS; ++it) {
        // ---- AF[r][c] = AT / (1 + sum_j BF[r][j] * KT[j][c]) ----
        {
            u64t acc[4][2];
            #pragma unroll
            for (int rr = 0; rr < 4; ++rr) { acc[rr][0] = 0ULL; acc[rr][1] = 0ULL; }

            #pragma unroll 8
            for (int j = 0; j < 64; ++j) {
                u64t k01, k23;
                lds_v2u64(ktb + (j << 8), k01, k23);       // KT[j][4tx..4tx+3]
                #pragma unroll
                for (int rr = 0; rr < 4; ++rr) {
                    u64t b = lds_u64(bfr[rr] + (j << 3));  // (BF[r][j], BF[r][j]) broadcast
                    acc[rr][0] = ffma2(b, k01, acc[rr][0]);
                    acc[rr][1] = ffma2(b, k23, acc[rr][1]);
                }
            }
            #pragma unroll
            for (int rr = 0; rr < 4; ++rr) {
                float s0, s1, s2, s3;
                unpack2(acc[rr][0], s0, s1);
                unpack2(acc[rr][1], s2, s3);
                float a0 = __fdividef(at[rr][0], 1.0f + s0);
                float a1 = __fdividef(at[rr][1], 1.0f + s1);
                float a2 = __fdividef(at[rr][2], 1.0f + s2);
                float a3 = __fdividef(at[rr][3], 1.0f + s3);
                aflast[rr][0] = a0; aflast[rr][1] = a1; aflast[rr][2] = a2; aflast[rr][3] = a3;
                float* dst = &AFd[(4 * ty + rr) * DUPSTR + (tx << 3)];
                *(float4*)dst       = make_float4(a0, a0, a1, a1);
                *(float4*)(dst + 4) = make_float4(a2, a2, a3, a3);
            }
        }
        __syncwarp();

        // ---- BF[r][c] = BT / (1 + sum_i AF[r][i] * K[i][c]) ----
        {
            u64t acc[4][2];
            #pragma unroll
            for (int rr = 0; rr < 4; ++rr) { acc[rr][0] = 0ULL; acc[rr][1] = 0ULL; }

            #pragma unroll 8
            for (int i = 0; i < 64; ++i) {
                u64t k01, k23;
                lds_v2u64(kb + (i << 8), k01, k23);        // K[i][4tx..4tx+3]
                #pragma unroll
                for (int rr = 0; rr < 4; ++rr) {
                    u64t a = lds_u64(afr[rr] + (i << 3));  // (AF[r][i], AF[r][i]) broadcast
                    acc[rr][0] = ffma2(a, k01, acc[rr][0]);
                    acc[rr][1] = ffma2(a, k23, acc[rr][1]);
                }
            }
            #pragma unroll
            for (int rr = 0; rr < 4; ++rr) {
                float s0, s1, s2, s3;
                unpack2(acc[rr][0], s0, s1);
                unpack2(acc[rr][1], s2, s3);
                float b0 = __fdividef(bt[rr][0], 1.0f + s0);
                float b1 = __fdividef(bt[rr][1], 1.0f + s1);
                float b2 = __fdividef(bt[rr][2], 1.0f + s2);
                float b3 = __fdividef(bt[rr][3], 1.0f + s3);
                bflast[rr][0] = b0; bflast[rr][1] = b1; bflast[rr][2] = b2; bflast[rr][3] = b3;
                float* dst = &BFd[(4 * ty + rr) * DUPSTR + (tx << 3)];
                *(float4*)dst       = make_float4(b0, b0, b1, b1);
                *(float4*)(dst + 4) = make_float4(b2, b2, b3, b3);
            }
        }
        __syncwarp();
    }

    // ---- park final AF/BF non-duplicated for the block-wide epilogue ----
    __syncthreads();                     // everyone done reading KT / dup tiles
    float* APark = KTsh;                 // 16 KB, no longer needed
    float* BPark = AFd;                  // reuse head of AF dup region
    #pragma unroll
    for (int rr = 0; rr < 4; ++rr) {
        const int off = ((4 * ty + rr) << 6) + (tx << 2);
        *(float4*)&APark[off] = make_float4(aflast[rr][0], aflast[rr][1], aflast[rr][2], aflast[rr][3]);
        *(float4*)&BPark[off] = make_float4(bflast[rr][0], bflast[rr][1], bflast[rr][2], bflast[rr][3]);
    }
    __syncthreads();

    // ---- C[r][i][j] = AF[r][i] * K[i][j] * BF[r][j] ----
    #pragma unroll 1
    for (int r = 0; r < 64; ++r) {
        float* crow = C + ((size_t)(row0 + r) << 12);   // 4096 floats per row
        const float* af_ = &APark[r << 6];
        const float* bf_ = &BPark[r << 6];
        #pragma unroll
        for (int q = 0; q < 4; ++q) {
            const int e = ((q << 8) + t) << 2;          // 0..4092 step 4
            const int i = e >> 6;
            const int j = e & 63;
            const float a = af_[i];
            float4 k4 = *(const float4*)&Ksh[e];
            float4 b4 = *(const float4*)&bf_[j];
            float4 o;
            o.x = a * k4.x * b4.x;
            o.y = a * k4.y * b4.y;
            o.z = a * k4.z * b4.z;
            o.w = a * k4.w * b4.w;
            *(float4*)&crow[e] = o;
        }
    }
}

extern "C" void kernel_launch(void* const* d_in, const int* in_sizes, int n_in,
                              void* d_out, int out_size)
{
    const float* AT = (const float*)d_in[0];   // (8192, 64)
    const float* BT = (const float*)d_in[1];   // (8192, 64)
    const float* sK = (const float*)d_in[2];   // (64, 64)
    float* C = (float*)d_out;                  // (8192, 64, 64)

    const int smem_bytes = SMEM_FLOATS * (int)sizeof(float);   // 100352
    cudaFuncSetAttribute(comp_layer_kernel,
                         cudaFuncAttributeMaxDynamicSharedMemorySize, smem_bytes);
    comp_layer_kernel<<<128, 256, smem_bytes>>>(AT, BT, sK, C);
}